// round 3
// baseline (speedup 1.0000x reference)
#include <cuda_runtime.h>
#include <stdint.h>

typedef unsigned long long u64;

// ---- packed fp32x2 primitives (SASS FFMA2 path, 2x fp32 throughput) ----
__device__ __forceinline__ u64 fma2(u64 a, u64 b, u64 c) {
    u64 d; asm("fma.rn.f32x2 %0, %1, %2, %3;" : "=l"(d) : "l"(a), "l"(b), "l"(c)); return d;
}
__device__ __forceinline__ u64 mul2(u64 a, u64 b) {
    u64 d; asm("mul.rn.f32x2 %0, %1, %2;" : "=l"(d) : "l"(a), "l"(b)); return d;
}
__device__ __forceinline__ u64 pack2(float lo, float hi) {
    u64 d; asm("mov.b64 %0, {%1, %2};" : "=l"(d) : "f"(lo), "f"(hi)); return d;
}
__device__ __forceinline__ void unpack2(u64 v, float& lo, float& hi) {
    asm("mov.b64 {%0, %1}, %2;" : "=f"(lo), "=f"(hi) : "l"(v));
}

// leaky(x) = max(x, 0.01x)  (valid elementwise for slope<1)
__device__ __forceinline__ u64 leaky2(u64 x) {
    const u64 SL = 0x3C23D70A3C23D70AULL;  // (0.01f, 0.01f)
    u64 s = mul2(x, SL);
    float xl, xh, sl, sh;
    unpack2(x, xl, xh); unpack2(s, sl, sh);
    return pack2(fmaxf(xl, sl), fmaxf(xh, sh));
}

struct Params { const float* p[20]; };  // [0..4]=ws_logs [5..9]=bs_logs [10..14]=ws_b [15..19]=bs_b

// One 8->8 layer applied to TWO packed row-pairs sharing the same weight load.
__device__ __forceinline__ void layer2pair(
    const u64* __restrict__ W, const u64* __restrict__ B,
    const u64* in0, const u64* in1, u64* out0, u64* out1, bool act)
{
#pragma unroll
    for (int j = 0; j < 8; j++) {
        u64 a0 = B[j], a1 = B[j];
#pragma unroll
        for (int i = 0; i < 8; i++) {
            u64 w = W[j * 8 + i];
            a0 = fma2(w, in0[i], a0);
            a1 = fma2(w, in1[i], a1);
        }
        out0[j] = act ? leaky2(a0) : a0;
        out1[j] = act ? leaky2(a1) : a1;
    }
}

// IOW: I/O width in floats per memory op (4 = float4, 2 = float2, 1 = scalar)
template <int IOW>
__global__ __launch_bounds__(128)
void affine_coupling_kernel(const float* __restrict__ z, float* __restrict__ out,
                            int batch, Params P)
{
    __shared__ u64 SW[2][5][64];  // duplicate-packed weights (w,w)
    __shared__ u64 SB[2][5][8];   // duplicate-packed biases

    const int tid = threadIdx.x;
    for (int idx = tid; idx < 640; idx += blockDim.x) {
        int m = idx / 320, r = idx % 320, l = r / 64, k = r % 64;
        float v = P.p[m * 10 + l][k];
        SW[m][l][k] = pack2(v, v);
    }
    for (int idx = tid; idx < 80; idx += blockDim.x) {
        int m = idx / 40, r = idx % 40, l = r / 8, k = r % 8;
        float v = P.p[m * 10 + 5 + l][k];
        SB[m][l][k] = pack2(v, v);
    }
    __syncthreads();

    const int lane = tid & 31;
    const int warp = tid >> 5;
    long long warpBase = ((long long)blockIdx.x * 4 + warp) * 128;
    if (warpBase >= batch) return;  // full warps only (handled by host grid calc)

    // Each thread: 2 pairs = 4 rows. Pair p = (warpBase + 64p + lane, +32).
    int rA[2], rB[2];
    float a[2][16], b[2][16];  // raw rows: a = row rA, b = row rB
#pragma unroll
    for (int p = 0; p < 2; p++) {
        rA[p] = (int)warpBase + p * 64 + lane;
        rB[p] = rA[p] + 32;
        const float* pa = z + (long long)rA[p] * 16;
        const float* pb = z + (long long)rB[p] * 16;
        if (IOW == 4) {
            const float4* pa4 = (const float4*)pa;
            const float4* pb4 = (const float4*)pb;
#pragma unroll
            for (int q = 0; q < 4; q++) {
                float4 va = pa4[q], vb = pb4[q];
                a[p][q*4+0]=va.x; a[p][q*4+1]=va.y; a[p][q*4+2]=va.z; a[p][q*4+3]=va.w;
                b[p][q*4+0]=vb.x; b[p][q*4+1]=vb.y; b[p][q*4+2]=vb.z; b[p][q*4+3]=vb.w;
            }
        } else if (IOW == 2) {
            const float2* pa2 = (const float2*)pa;
            const float2* pb2 = (const float2*)pb;
#pragma unroll
            for (int q = 0; q < 8; q++) {
                float2 va = pa2[q], vb = pb2[q];
                a[p][q*2+0]=va.x; a[p][q*2+1]=va.y;
                b[p][q*2+0]=vb.x; b[p][q*2+1]=vb.y;
            }
        } else {
#pragma unroll
            for (int q = 0; q < 16; q++) { a[p][q] = pa[q]; b[p][q] = pb[q]; }
        }
    }

    // Pack into f32x2 lanes: (rowA, rowB) per 64-bit register.
    u64 zl[2][8], zr[2][8];
#pragma unroll
    for (int p = 0; p < 2; p++) {
#pragma unroll
        for (int q = 0; q < 8; q++) {
            zl[p][q] = pack2(a[p][q],     b[p][q]);
            zr[p][q] = pack2(a[p][8 + q], b[p][8 + q]);
        }
    }

    // Left half passthrough: store immediately.
#pragma unroll
    for (int p = 0; p < 2; p++) {
        float* oa = out + (long long)rA[p] * 16;
        float* ob = out + (long long)rB[p] * 16;
        if (IOW == 4) {
            float4* oa4 = (float4*)oa; float4* ob4 = (float4*)ob;
            oa4[0] = make_float4(a[p][0], a[p][1], a[p][2], a[p][3]);
            oa4[1] = make_float4(a[p][4], a[p][5], a[p][6], a[p][7]);
            ob4[0] = make_float4(b[p][0], b[p][1], b[p][2], b[p][3]);
            ob4[1] = make_float4(b[p][4], b[p][5], b[p][6], b[p][7]);
        } else if (IOW == 2) {
            float2* oa2 = (float2*)oa; float2* ob2 = (float2*)ob;
#pragma unroll
            for (int q = 0; q < 4; q++) {
                oa2[q] = make_float2(a[p][q*2], a[p][q*2+1]);
                ob2[q] = make_float2(b[p][q*2], b[p][q*2+1]);
            }
        } else {
#pragma unroll
            for (int q = 0; q < 8; q++) { oa[q] = a[p][q]; ob[q] = b[p][q]; }
        }
    }

    // Layer 0 of BOTH chains consumes zl, then zl is dead (limits reg pressure).
    u64 s[2][8], bb[2][8], t[2][8], ls[2][8], bv[2][8];
    layer2pair(SW[0][0], SB[0][0], zl[0], zl[1], s[0],  s[1],  true);
    layer2pair(SW[1][0], SB[1][0], zl[0], zl[1], bb[0], bb[1], true);

    // log_s chain
    layer2pair(SW[0][1], SB[0][1], s[0], s[1], t[0], t[1], true);
    layer2pair(SW[0][2], SB[0][2], t[0], t[1], s[0], s[1], true);
    layer2pair(SW[0][3], SB[0][3], s[0], s[1], t[0], t[1], true);
    layer2pair(SW[0][4], SB[0][4], t[0], t[1], ls[0], ls[1], false);

    // b chain
    layer2pair(SW[1][1], SB[1][1], bb[0], bb[1], t[0],  t[1],  true);
    layer2pair(SW[1][2], SB[1][2], t[0],  t[1],  bb[0], bb[1], true);
    layer2pair(SW[1][3], SB[1][3], bb[0], bb[1], t[0],  t[1],  true);
    layer2pair(SW[1][4], SB[1][4], t[0],  t[1],  bv[0], bv[1], false);

    // yr = exp(log_s) * zr + b
#pragma unroll
    for (int p = 0; p < 2; p++) {
        float yA[8], yB[8];
#pragma unroll
        for (int j = 0; j < 8; j++) {
            float lA, lB, bA, bB, zA, zB;
            unpack2(ls[p][j], lA, lB);
            unpack2(bv[p][j], bA, bB);
            unpack2(zr[p][j], zA, zB);
            yA[j] = fmaf(__expf(lA), zA, bA);
            yB[j] = fmaf(__expf(lB), zB, bB);
        }
        float* oa = out + (long long)rA[p] * 16 + 8;
        float* ob = out + (long long)rB[p] * 16 + 8;
        if (IOW == 4) {
            float4* oa4 = (float4*)oa; float4* ob4 = (float4*)ob;
            oa4[0] = make_float4(yA[0], yA[1], yA[2], yA[3]);
            oa4[1] = make_float4(yA[4], yA[5], yA[6], yA[7]);
            ob4[0] = make_float4(yB[0], yB[1], yB[2], yB[3]);
            ob4[1] = make_float4(yB[4], yB[5], yB[6], yB[7]);
        } else if (IOW == 2) {
            float2* oa2 = (float2*)oa; float2* ob2 = (float2*)ob;
#pragma unroll
            for (int q = 0; q < 4; q++) {
                oa2[q] = make_float2(yA[q*2], yA[q*2+1]);
                ob2[q] = make_float2(yB[q*2], yB[q*2+1]);
            }
        } else {
#pragma unroll
            for (int q = 0; q < 8; q++) { oa[q] = yA[q]; ob[q] = yB[q]; }
        }
    }
}

extern "C" void kernel_launch(void* const* d_in, const int* in_sizes, int n_in,
                              void* d_out, int out_size)
{
    // ---- locate z: the (unique) huge input ----
    int zi = 0;
    for (int i = 0; i < n_in; i++) {
        if (in_sizes[i] > in_sizes[zi]) zi = i;
    }
    const float* z = (const float*)d_in[zi];
    long long batchLL = (long long)in_sizes[zi] / 16;
    int batch = (int)batchLL;
    float* out = (float*)d_out;

    // ---- build the 20 layer-parameter pointers, layout-adaptively ----
    // Semantic order: ws_logs[0..4], bs_logs[0..4], ws_b[0..4], bs_b[0..4]
    Params P;
    if (n_in >= 21) {
        // 21 separate tensors in signature order (z first).
        int k = 0;
        for (int i = 0; i < n_in && k < 20; i++) {
            if (i == zi) continue;
            P.p[k++] = (const float*)d_in[i];
        }
    } else {
        // Lists stacked into single tensors. Expected groups (in order after z):
        // ws_logs:5*64, bs_logs:5*8, ws_b:5*64, bs_b:5*8 — but tolerate any
        // ordering of the four blobs by dispatching on each blob's size.
        int wslot = 0, bslot = 0;  // 0 -> logs, 1 -> b
        for (int i = 0; i < n_in; i++) {
            if (i == zi) continue;
            const float* base = (const float*)d_in[i];
            int sz = in_sizes[i];
            if (sz == 320) {            // stacked weights (5,8,8)
                int m = (wslot++ == 0) ? 0 : 1;
                for (int l = 0; l < 5; l++) P.p[m * 10 + l] = base + 64 * l;
            } else if (sz == 40) {      // stacked biases (5,8)
                int m = (bslot++ == 0) ? 0 : 1;
                for (int l = 0; l < 5; l++) P.p[m * 10 + 5 + l] = base + 8 * l;
            }
        }
    }

    int rowsPerBlock = 512;                // 128 threads * 4 rows
    int grid = (int)((batchLL + rowsPerBlock - 1) / rowsPerBlock);

    uintptr_t mis = (uintptr_t)z | (uintptr_t)out;
    if ((mis & 15) == 0) {
        affine_coupling_kernel<4><<<grid, 128>>>(z, out, batch, P);
    } else if ((mis & 7) == 0) {
        affine_coupling_kernel<2><<<grid, 128>>>(z, out, batch, P);
    } else {
        affine_coupling_kernel<1><<<grid, 128>>>(z, out, batch, P);
    }
}